// round 2
// baseline (speedup 1.0000x reference)
#include <cuda_runtime.h>
#include <cstdint>
#include <cstddef>

#define NNODES   50000
#define EDGESMAX 800000
#define HDIM     256   // NUM_HEADS * OUT_DIM

// -------- scratch (static __device__ arrays; no allocation allowed) --------
__device__ float g_Q[(size_t)NNODES * HDIM];
__device__ float g_K[(size_t)NNODES * HDIM];
__device__ float g_V[(size_t)NNODES * HDIM];
__device__ float g_score[(size_t)EDGESMAX * 8];
__device__ float g_z[(size_t)NNODES * 8];

__device__ __forceinline__ uint32_t f2tf32(float x) {
    uint32_t r;
    asm("cvt.rna.tf32.f32 %0, %1;" : "=r"(r) : "f"(x));
    return r;
}

// ---------------------------------------------------------------------------
// Kernel 0: zero the output accumulator and the softmax denominators
// ---------------------------------------------------------------------------
__global__ void zero_kernel(float* __restrict__ out, int n_out, int n_nodes) {
    int total = n_out + n_nodes * 8;
    for (int i = blockIdx.x * blockDim.x + threadIdx.x; i < total;
         i += gridDim.x * blockDim.x) {
        if (i < n_out) out[i] = 0.0f;
        else           g_z[i - n_out] = 0.0f;
    }
}

// ---------------------------------------------------------------------------
// Kernel 1: fused QKV projection.  out[n, j] = sum_i h[n,i] * W[j,i] + b[j]
// TF32 mma.sync m16n8k8, block tile 128x128x32, warp tile 64x32.
// grid.y in [0,6): two 128-wide column blocks per weight matrix (Q,K,V).
// ---------------------------------------------------------------------------
__global__ __launch_bounds__(256) void qkv_gemm(
    const float* __restrict__ h,
    const float* __restrict__ Wq, const float* __restrict__ bq,
    const float* __restrict__ Wk, const float* __restrict__ bk,
    const float* __restrict__ Wv, const float* __restrict__ bv,
    int Nrows)
{
    __shared__ uint32_t As[128 * 36];   // padded stride 36 -> conflict-free frag loads
    __shared__ uint32_t Bs[128 * 36];

    const int tid  = threadIdx.x;
    const int lane = tid & 31;
    const int warp = tid >> 5;
    const int wm = warp >> 2;           // 0..1 : 64-row slice
    const int wn = warp & 3;            // 0..3 : 32-col slice
    const int bm = blockIdx.x;
    const int bn = blockIdx.y;

    const float* W;  const float* bias;  float* target;
    if (bn < 2)      { W = Wq; bias = bq; target = g_Q; }
    else if (bn < 4) { W = Wk; bias = bk; target = g_K; }
    else             { W = Wv; bias = bv; target = g_V; }
    const int ncol0 = (bn & 1) * 128;   // column offset within the 256-wide matrix

    float acc[4][4][4];
    #pragma unroll
    for (int i = 0; i < 4; i++)
        #pragma unroll
        for (int j = 0; j < 4; j++)
            #pragma unroll
            for (int k = 0; k < 4; k++) acc[i][j][k] = 0.0f;

    const int lr = tid >> 3;          // 0..31
    const int lc = (tid & 7) * 4;     // 0,4,..,28

    for (int kb = 0; kb < 256; kb += 32) {
        // ---- global -> shared (with tf32 rounding) ----
        #pragma unroll
        for (int i = 0; i < 4; i++) {
            int r = lr + i * 32;
            int grow = bm * 128 + r;
            float4 v = make_float4(0.f, 0.f, 0.f, 0.f);
            if (grow < Nrows)
                v = *(const float4*)(h + (size_t)grow * 256 + kb + lc);
            uint32_t* s = &As[r * 36 + lc];
            s[0] = f2tf32(v.x); s[1] = f2tf32(v.y);
            s[2] = f2tf32(v.z); s[3] = f2tf32(v.w);
        }
        #pragma unroll
        for (int i = 0; i < 4; i++) {
            int r = lr + i * 32;                 // n index within tile (always valid)
            float4 v = *(const float4*)(W + (size_t)(ncol0 + r) * 256 + kb + lc);
            uint32_t* s = &Bs[r * 36 + lc];
            s[0] = f2tf32(v.x); s[1] = f2tf32(v.y);
            s[2] = f2tf32(v.z); s[3] = f2tf32(v.w);
        }
        __syncthreads();

        // ---- compute 4 k-steps of 8 ----
        #pragma unroll
        for (int ks = 0; ks < 4; ks++) {
            const int k0 = ks * 8;
            uint32_t a[4][4], b[4][2];
            #pragma unroll
            for (int mt = 0; mt < 4; mt++) {
                int r = wm * 64 + mt * 16 + (lane >> 2);
                int c = k0 + (lane & 3);
                a[mt][0] = As[r * 36 + c];
                a[mt][1] = As[(r + 8) * 36 + c];
                a[mt][2] = As[r * 36 + c + 4];
                a[mt][3] = As[(r + 8) * 36 + c + 4];
            }
            #pragma unroll
            for (int nt = 0; nt < 4; nt++) {
                int n = wn * 32 + nt * 8 + (lane >> 2);
                int c = k0 + (lane & 3);
                b[nt][0] = Bs[n * 36 + c];
                b[nt][1] = Bs[n * 36 + c + 4];
            }
            #pragma unroll
            for (int mt = 0; mt < 4; mt++)
                #pragma unroll
                for (int nt = 0; nt < 4; nt++)
                    asm volatile(
                        "mma.sync.aligned.m16n8k8.row.col.f32.tf32.tf32.f32 "
                        "{%0,%1,%2,%3}, {%4,%5,%6,%7}, {%8,%9}, {%0,%1,%2,%3};"
                        : "+f"(acc[mt][nt][0]), "+f"(acc[mt][nt][1]),
                          "+f"(acc[mt][nt][2]), "+f"(acc[mt][nt][3])
                        : "r"(a[mt][0]), "r"(a[mt][1]), "r"(a[mt][2]), "r"(a[mt][3]),
                          "r"(b[nt][0]), "r"(b[nt][1]));
        }
        __syncthreads();
    }

    // ---- epilogue: add bias, store to Q/K/V scratch ----
    #pragma unroll
    for (int mt = 0; mt < 4; mt++) {
        int r0 = wm * 64 + mt * 16 + (lane >> 2);
        #pragma unroll
        for (int nt = 0; nt < 4; nt++) {
            int c0 = wn * 32 + nt * 8 + (lane & 3) * 2;
            #pragma unroll
            for (int cc = 0; cc < 4; cc++) {
                int r = r0 + ((cc >= 2) ? 8 : 0);
                int c = c0 + (cc & 1);
                int grow = bm * 128 + r;
                if (grow < Nrows) {
                    int j = ncol0 + c;
                    target[(size_t)grow * 256 + j] = acc[mt][nt][cc] + bias[j];
                }
            }
        }
    }
}

// ---------------------------------------------------------------------------
// Kernel 2: per-edge attention scores + segment-sum denominator.
// One warp per edge; each lane covers 4 consecutive channels, twice.
// ---------------------------------------------------------------------------
__global__ __launch_bounds__(256) void score_kernel(
    const int* __restrict__ src, const int* __restrict__ dst, int E)
{
    int e = (blockIdx.x * blockDim.x + threadIdx.x) >> 5;
    if (e >= E) return;
    const int lane = threadIdx.x & 31;
    const int s = src[e];
    const int d = dst[e];

    const float4* Kr = (const float4*)(g_K + (size_t)s * 256);
    const float4* Qr = (const float4*)(g_Q + (size_t)d * 256);
    float4 k0 = Kr[lane],      q0 = Qr[lane];       // heads 0..3
    float4 k1 = Kr[lane + 32], q1 = Qr[lane + 32];  // heads 4..7

    float p0 = k0.x * q0.x + k0.y * q0.y + k0.z * q0.z + k0.w * q0.w;
    float p1 = k1.x * q1.x + k1.y * q1.y + k1.z * q1.z + k1.w * q1.w;
    #pragma unroll
    for (int off = 4; off; off >>= 1) {
        p0 += __shfl_down_sync(0xffffffffu, p0, off);
        p1 += __shfl_down_sync(0xffffffffu, p1, off);
    }
    if ((lane & 7) == 0) {
        const float inv = 0.17677669529663687f;   // 1/sqrt(32)
        int h0 = lane >> 3;                        // 0..3
        float sc0 = expf(fminf(fmaxf(p0 * inv, -5.0f), 5.0f));
        float sc1 = expf(fminf(fmaxf(p1 * inv, -5.0f), 5.0f));
        g_score[(size_t)e * 8 + h0]     = sc0;
        g_score[(size_t)e * 8 + h0 + 4] = sc1;
        atomicAdd(&g_z[(size_t)d * 8 + h0],     sc0);
        atomicAdd(&g_z[(size_t)d * 8 + h0 + 4], sc1);
    }
}

// ---------------------------------------------------------------------------
// Kernel 3: weighted aggregation.  out[dst, h, :] += (score/z[dst,h]) * V[src, h, :]
// One warp per edge; 8 REDG fp32 adds per lane.
// ---------------------------------------------------------------------------
__global__ __launch_bounds__(256) void agg_kernel(
    const int* __restrict__ src, const int* __restrict__ dst,
    float* __restrict__ out, int E)
{
    int e = (blockIdx.x * blockDim.x + threadIdx.x) >> 5;
    if (e >= E) return;
    const int lane = threadIdx.x & 31;
    const int s = src[e];
    const int d = dst[e];

    int h0 = lane >> 3;        // 0..3
    int h1 = h0 + 4;           // 4..7
    float a0 = g_score[(size_t)e * 8 + h0] / g_z[(size_t)d * 8 + h0];
    float a1 = g_score[(size_t)e * 8 + h1] / g_z[(size_t)d * 8 + h1];

    const float4* Vr = (const float4*)(g_V + (size_t)s * 256);
    float4 v0 = Vr[lane];
    float4 v1 = Vr[lane + 32];

    float* o = out + (size_t)d * 256;
    int c0 = 4 * lane;
    atomicAdd(o + c0 + 0, a0 * v0.x);
    atomicAdd(o + c0 + 1, a0 * v0.y);
    atomicAdd(o + c0 + 2, a0 * v0.z);
    atomicAdd(o + c0 + 3, a0 * v0.w);
    atomicAdd(o + 128 + c0 + 0, a1 * v1.x);
    atomicAdd(o + 128 + c0 + 1, a1 * v1.y);
    atomicAdd(o + 128 + c0 + 2, a1 * v1.z);
    atomicAdd(o + 128 + c0 + 3, a1 * v1.w);
}

// ---------------------------------------------------------------------------
extern "C" void kernel_launch(void* const* d_in, const int* in_sizes, int n_in,
                              void* d_out, int out_size)
{
    const float* h  = (const float*)d_in[0];
    const float* Wq = (const float*)d_in[1];
    const float* bq = (const float*)d_in[2];
    const float* Wk = (const float*)d_in[3];
    const float* bk = (const float*)d_in[4];
    const float* Wv = (const float*)d_in[5];
    const float* bv = (const float*)d_in[6];
    const int*   src = (const int*)d_in[7];
    const int*   dst = (const int*)d_in[8];
    float* out = (float*)d_out;

    const int N = in_sizes[0] / 256;   // 50000
    const int E = in_sizes[7];         // 800000

    int totz = out_size + N * 8;
    zero_kernel<<<(totz + 255) / 256, 256>>>(out, out_size, N);

    dim3 grid((N + 127) / 128, 6);
    qkv_gemm<<<grid, 256>>>(h, Wq, bq, Wk, bk, Wv, bv, N);

    score_kernel<<<(E + 7) / 8, 256>>>(src, dst, E);
    agg_kernel<<<(E + 7) / 8, 256>>>(src, dst, out, E);
}

// round 3
// speedup vs baseline: 2.0967x; 2.0967x over previous
#include <cuda_runtime.h>
#include <cstdint>
#include <cstddef>

#define NNODES   50000
#define EDGESMAX 800000
#define HDIM     256   // NUM_HEADS * OUT_DIM

// -------- scratch (static __device__ arrays; no allocation allowed) --------
__device__ float g_Q[(size_t)NNODES * HDIM];
__device__ float g_K[(size_t)NNODES * HDIM];
__device__ float g_V[(size_t)NNODES * HDIM];
__device__ float g_score[(size_t)EDGESMAX * 8];
__device__ int   g_deg[NNODES];
__device__ int   g_cursor[NNODES];
__device__ int   g_rowptr[NNODES + 1];
__device__ int   g_csr_src[EDGESMAX];

__device__ __forceinline__ uint32_t f2tf32(float x) {
    uint32_t r;
    asm("cvt.rna.tf32.f32 %0, %1;" : "=r"(r) : "f"(x));
    return r;
}

// ---------------------------------------------------------------------------
// CSR build: zero counters -> histogram -> exclusive scan -> scatter
// ---------------------------------------------------------------------------
__global__ void zero_counters(int n_nodes) {
    int i = blockIdx.x * blockDim.x + threadIdx.x;
    if (i < n_nodes) { g_deg[i] = 0; g_cursor[i] = 0; }
}

__global__ void hist_kernel(const int* __restrict__ dst, int E) {
    int e = blockIdx.x * blockDim.x + threadIdx.x;
    if (e < E) atomicAdd(&g_deg[dst[e]], 1);
}

// single-block exclusive scan (warp-scan + cross-warp), 1024 threads
__global__ __launch_bounds__(1024) void scan_kernel(int n) {
    __shared__ int warp_sums[32];
    __shared__ int s_carry;
    const int tid  = threadIdx.x;
    const int lane = tid & 31;
    const int wid  = tid >> 5;
    if (tid == 0) s_carry = 0;
    __syncthreads();

    for (int base = 0; base < n; base += 1024) {
        int i = base + tid;
        int v = (i < n) ? g_deg[i] : 0;
        // inclusive warp scan
        int x = v;
        #pragma unroll
        for (int off = 1; off < 32; off <<= 1) {
            int t = __shfl_up_sync(0xffffffffu, x, off);
            if (lane >= off) x += t;
        }
        if (lane == 31) warp_sums[wid] = x;
        __syncthreads();
        if (wid == 0) {
            int w = (lane < 32) ? warp_sums[lane] : 0;
            #pragma unroll
            for (int off = 1; off < 32; off <<= 1) {
                int t = __shfl_up_sync(0xffffffffu, w, off);
                if (lane >= off) w += t;
            }
            warp_sums[lane] = w;               // inclusive over warps
        }
        __syncthreads();
        int warp_off = (wid > 0) ? warp_sums[wid - 1] : 0;
        int incl = x + warp_off;
        if (i < n) g_rowptr[i] = s_carry + incl - v;   // exclusive
        __syncthreads();
        if (tid == 1023) s_carry += warp_sums[31];
        __syncthreads();
    }
    if (tid == 0) g_rowptr[n] = s_carry;
}

__global__ void scatter_kernel(const int* __restrict__ src,
                               const int* __restrict__ dst, int E) {
    int e = blockIdx.x * blockDim.x + threadIdx.x;
    if (e < E) {
        int d = dst[e];
        int pos = g_rowptr[d] + atomicAdd(&g_cursor[d], 1);
        g_csr_src[pos] = src[e];
    }
}

// ---------------------------------------------------------------------------
// Kernel 1: fused QKV projection.  out[n, j] = sum_i h[n,i] * W[j,i] + b[j]
// TF32 mma.sync m16n8k8, block tile 128x128x32, warp tile 64x32.
// ---------------------------------------------------------------------------
__global__ __launch_bounds__(256) void qkv_gemm(
    const float* __restrict__ h,
    const float* __restrict__ Wq, const float* __restrict__ bq,
    const float* __restrict__ Wk, const float* __restrict__ bk,
    const float* __restrict__ Wv, const float* __restrict__ bv,
    int Nrows)
{
    __shared__ uint32_t As[128 * 36];
    __shared__ uint32_t Bs[128 * 36];

    const int tid  = threadIdx.x;
    const int lane = tid & 31;
    const int warp = tid >> 5;
    const int wm = warp >> 2;
    const int wn = warp & 3;
    const int bm = blockIdx.x;
    const int bn = blockIdx.y;

    const float* W;  const float* bias;  float* target;
    if (bn < 2)      { W = Wq; bias = bq; target = g_Q; }
    else if (bn < 4) { W = Wk; bias = bk; target = g_K; }
    else             { W = Wv; bias = bv; target = g_V; }
    const int ncol0 = (bn & 1) * 128;

    float acc[4][4][4];
    #pragma unroll
    for (int i = 0; i < 4; i++)
        #pragma unroll
        for (int j = 0; j < 4; j++)
            #pragma unroll
            for (int k = 0; k < 4; k++) acc[i][j][k] = 0.0f;

    const int lr = tid >> 3;
    const int lc = (tid & 7) * 4;

    for (int kb = 0; kb < 256; kb += 32) {
        #pragma unroll
        for (int i = 0; i < 4; i++) {
            int r = lr + i * 32;
            int grow = bm * 128 + r;
            float4 v = make_float4(0.f, 0.f, 0.f, 0.f);
            if (grow < Nrows)
                v = *(const float4*)(h + (size_t)grow * 256 + kb + lc);
            uint32_t* s = &As[r * 36 + lc];
            s[0] = f2tf32(v.x); s[1] = f2tf32(v.y);
            s[2] = f2tf32(v.z); s[3] = f2tf32(v.w);
        }
        #pragma unroll
        for (int i = 0; i < 4; i++) {
            int r = lr + i * 32;
            float4 v = *(const float4*)(W + (size_t)(ncol0 + r) * 256 + kb + lc);
            uint32_t* s = &Bs[r * 36 + lc];
            s[0] = f2tf32(v.x); s[1] = f2tf32(v.y);
            s[2] = f2tf32(v.z); s[3] = f2tf32(v.w);
        }
        __syncthreads();

        #pragma unroll
        for (int ks = 0; ks < 4; ks++) {
            const int k0 = ks * 8;
            uint32_t a[4][4], b[4][2];
            #pragma unroll
            for (int mt = 0; mt < 4; mt++) {
                int r = wm * 64 + mt * 16 + (lane >> 2);
                int c = k0 + (lane & 3);
                a[mt][0] = As[r * 36 + c];
                a[mt][1] = As[(r + 8) * 36 + c];
                a[mt][2] = As[r * 36 + c + 4];
                a[mt][3] = As[(r + 8) * 36 + c + 4];
            }
            #pragma unroll
            for (int nt = 0; nt < 4; nt++) {
                int n = wn * 32 + nt * 8 + (lane >> 2);
                int c = k0 + (lane & 3);
                b[nt][0] = Bs[n * 36 + c];
                b[nt][1] = Bs[n * 36 + c + 4];
            }
            #pragma unroll
            for (int mt = 0; mt < 4; mt++)
                #pragma unroll
                for (int nt = 0; nt < 4; nt++)
                    asm volatile(
                        "mma.sync.aligned.m16n8k8.row.col.f32.tf32.tf32.f32 "
                        "{%0,%1,%2,%3}, {%4,%5,%6,%7}, {%8,%9}, {%0,%1,%2,%3};"
                        : "+f"(acc[mt][nt][0]), "+f"(acc[mt][nt][1]),
                          "+f"(acc[mt][nt][2]), "+f"(acc[mt][nt][3])
                        : "r"(a[mt][0]), "r"(a[mt][1]), "r"(a[mt][2]), "r"(a[mt][3]),
                          "r"(b[nt][0]), "r"(b[nt][1]));
        }
        __syncthreads();
    }

    #pragma unroll
    for (int mt = 0; mt < 4; mt++) {
        int r0 = wm * 64 + mt * 16 + (lane >> 2);
        #pragma unroll
        for (int nt = 0; nt < 4; nt++) {
            int c0 = wn * 32 + nt * 8 + (lane & 3) * 2;
            #pragma unroll
            for (int cc = 0; cc < 4; cc++) {
                int r = r0 + ((cc >= 2) ? 8 : 0);
                int c = c0 + (cc & 1);
                int grow = bm * 128 + r;
                if (grow < Nrows) {
                    int j = ncol0 + c;
                    target[(size_t)grow * 256 + j] = acc[mt][nt][cc] + bias[j];
                }
            }
        }
    }
}

// ---------------------------------------------------------------------------
// Kernel 2 (fused): one warp per destination node.
// Pass 1: K[src]·Q[dst] per in-edge -> scores (CSR order) + register z.
// Pass 2: out[dst] = sum (score/z) * V[src]; single coalesced row store.
// ---------------------------------------------------------------------------
__global__ __launch_bounds__(256) void attn_fused(
    float* __restrict__ out, int n_nodes)
{
    const int node = (blockIdx.x * blockDim.x + threadIdx.x) >> 5;
    if (node >= n_nodes) return;
    const int lane = threadIdx.x & 31;
    const unsigned FULL = 0xffffffffu;

    const int beg = g_rowptr[node];
    const int end = g_rowptr[node + 1];

    // Q row (register-resident): lane covers channels [4*lane, 4*lane+3] and +128
    const float4* Qr = (const float4*)(g_Q + (size_t)node * 256);
    const float4 q0 = Qr[lane];
    const float4 q1 = Qr[lane + 32];

    const int h0 = lane >> 3;        // head for acc0: 0..3
    float z0 = 0.0f, z1 = 0.0f;      // valid at lanes 0,8,16,24

    // ---- pass 1: scores + z ----
    for (int i = beg; i < end; i++) {
        const int s = g_csr_src[i];
        const float4* Kr = (const float4*)(g_K + (size_t)s * 256);
        float4 k0 = Kr[lane];
        float4 k1 = Kr[lane + 32];
        float p0 = k0.x * q0.x + k0.y * q0.y + k0.z * q0.z + k0.w * q0.w;
        float p1 = k1.x * q1.x + k1.y * q1.y + k1.z * q1.z + k1.w * q1.w;
        #pragma unroll
        for (int off = 4; off; off >>= 1) {
            p0 += __shfl_down_sync(FULL, p0, off);
            p1 += __shfl_down_sync(FULL, p1, off);
        }
        if ((lane & 7) == 0) {
            const float inv = 0.17677669529663687f;   // 1/sqrt(32)
            float sc0 = expf(fminf(fmaxf(p0 * inv, -5.0f), 5.0f));
            float sc1 = expf(fminf(fmaxf(p1 * inv, -5.0f), 5.0f));
            g_score[(size_t)i * 8 + h0]     = sc0;
            g_score[(size_t)i * 8 + h0 + 4] = sc1;
            z0 += sc0;
            z1 += sc1;
        }
    }

    // broadcast per-head 1/z to all lanes of the head group
    const int src_lane = lane & ~7;
    float zz0 = __shfl_sync(FULL, z0, src_lane);
    float zz1 = __shfl_sync(FULL, z1, src_lane);
    const float rz0 = (zz0 > 0.0f) ? 1.0f / zz0 : 0.0f;
    const float rz1 = (zz1 > 0.0f) ? 1.0f / zz1 : 0.0f;

    // ---- pass 2: weighted aggregation ----
    float4 acc0 = make_float4(0.f, 0.f, 0.f, 0.f);
    float4 acc1 = make_float4(0.f, 0.f, 0.f, 0.f);
    for (int i = beg; i < end; i++) {
        const int s = g_csr_src[i];
        const float a0 = g_score[(size_t)i * 8 + h0]     * rz0;
        const float a1 = g_score[(size_t)i * 8 + h0 + 4] * rz1;
        const float4* Vr = (const float4*)(g_V + (size_t)s * 256);
        float4 v0 = Vr[lane];
        float4 v1 = Vr[lane + 32];
        acc0.x += a0 * v0.x; acc0.y += a0 * v0.y;
        acc0.z += a0 * v0.z; acc0.w += a0 * v0.w;
        acc1.x += a1 * v1.x; acc1.y += a1 * v1.y;
        acc1.z += a1 * v1.z; acc1.w += a1 * v1.w;
    }

    float4* o = (float4*)(out + (size_t)node * 256);
    o[lane]      = acc0;
    o[lane + 32] = acc1;
}

// ---------------------------------------------------------------------------
extern "C" void kernel_launch(void* const* d_in, const int* in_sizes, int n_in,
                              void* d_out, int out_size)
{
    const float* h  = (const float*)d_in[0];
    const float* Wq = (const float*)d_in[1];
    const float* bq = (const float*)d_in[2];
    const float* Wk = (const float*)d_in[3];
    const float* bk = (const float*)d_in[4];
    const float* Wv = (const float*)d_in[5];
    const float* bv = (const float*)d_in[6];
    const int*   src = (const int*)d_in[7];
    const int*   dst = (const int*)d_in[8];
    float* out = (float*)d_out;

    const int N = in_sizes[0] / 256;   // 50000
    const int E = in_sizes[7];         // 800000

    // CSR build
    zero_counters<<<(N + 255) / 256, 256>>>(N);
    hist_kernel<<<(E + 255) / 256, 256>>>(dst, E);
    scan_kernel<<<1, 1024>>>(N);
    scatter_kernel<<<(E + 255) / 256, 256>>>(src, dst, E);

    // QKV projections (TF32 tensor-core GEMM)
    dim3 grid((N + 127) / 128, 6);
    qkv_gemm<<<grid, 256>>>(h, Wq, bq, Wk, bk, Wv, bv, N);

    // Fused score + softmax + aggregation, one warp per dst node
    attn_fused<<<(N * 32 + 255) / 256, 256>>>(out, N);
}

// round 4
// speedup vs baseline: 2.1470x; 1.0240x over previous
#include <cuda_runtime.h>
#include <cstdint>
#include <cstddef>

#define NNODES   50000
#define EDGESMAX 800000
#define HDIM     256   // NUM_HEADS * OUT_DIM

// -------- scratch (static __device__ arrays; no allocation allowed) --------
__device__ float g_Q[(size_t)NNODES * HDIM];
__device__ float g_K[(size_t)NNODES * HDIM];
__device__ float g_V[(size_t)NNODES * HDIM];
__device__ int   g_deg[NNODES];
__device__ int   g_cursor[NNODES];
__device__ int   g_rowptr[NNODES + 1];
__device__ int   g_csr_src[EDGESMAX];

__device__ __forceinline__ uint32_t f2tf32(float x) {
    uint32_t r;
    asm("cvt.rna.tf32.f32 %0, %1;" : "=r"(r) : "f"(x));
    return r;
}

// ---------------------------------------------------------------------------
// CSR build: zero deg -> histogram -> exclusive scan (also seeds cursor) -> scatter
// ---------------------------------------------------------------------------
__global__ void zero_deg(int n_nodes) {
    int i = blockIdx.x * blockDim.x + threadIdx.x;
    if (i < n_nodes) g_deg[i] = 0;
}

__global__ void hist_kernel(const int* __restrict__ dst, int E) {
    int e = blockIdx.x * blockDim.x + threadIdx.x;
    if (e < E) atomicAdd(&g_deg[dst[e]], 1);
}

// single-block exclusive scan (warp-scan + cross-warp), 1024 threads
__global__ __launch_bounds__(1024) void scan_kernel(int n) {
    __shared__ int warp_sums[32];
    __shared__ int s_carry;
    const int tid  = threadIdx.x;
    const int lane = tid & 31;
    const int wid  = tid >> 5;
    if (tid == 0) s_carry = 0;
    __syncthreads();

    for (int base = 0; base < n; base += 1024) {
        int i = base + tid;
        int v = (i < n) ? g_deg[i] : 0;
        int x = v;
        #pragma unroll
        for (int off = 1; off < 32; off <<= 1) {
            int t = __shfl_up_sync(0xffffffffu, x, off);
            if (lane >= off) x += t;
        }
        if (lane == 31) warp_sums[wid] = x;
        __syncthreads();
        if (wid == 0) {
            int w = warp_sums[lane];
            #pragma unroll
            for (int off = 1; off < 32; off <<= 1) {
                int t = __shfl_up_sync(0xffffffffu, w, off);
                if (lane >= off) w += t;
            }
            warp_sums[lane] = w;
        }
        __syncthreads();
        int warp_off = (wid > 0) ? warp_sums[wid - 1] : 0;
        int excl = s_carry + x + warp_off - v;
        if (i < n) { g_rowptr[i] = excl; g_cursor[i] = excl; }
        __syncthreads();
        if (tid == 1023) s_carry += warp_sums[31];
        __syncthreads();
    }
    if (tid == 0) g_rowptr[n] = s_carry;
}

__global__ void scatter_kernel(const int* __restrict__ src,
                               const int* __restrict__ dst, int E) {
    int e = blockIdx.x * blockDim.x + threadIdx.x;
    if (e < E) {
        int pos = atomicAdd(&g_cursor[dst[e]], 1);
        g_csr_src[pos] = src[e];
    }
}

// ---------------------------------------------------------------------------
// Kernel 1: fused QKV projection.  TF32 mma m16n8k8, tile 128x128x32.
// ---------------------------------------------------------------------------
__global__ __launch_bounds__(256) void qkv_gemm(
    const float* __restrict__ h,
    const float* __restrict__ Wq, const float* __restrict__ bq,
    const float* __restrict__ Wk, const float* __restrict__ bk,
    const float* __restrict__ Wv, const float* __restrict__ bv,
    int Nrows)
{
    __shared__ uint32_t As[128 * 36];
    __shared__ uint32_t Bs[128 * 36];

    const int tid  = threadIdx.x;
    const int lane = tid & 31;
    const int warp = tid >> 5;
    const int wm = warp >> 2;
    const int wn = warp & 3;
    const int bm = blockIdx.x;
    const int bn = blockIdx.y;

    const float* W;  const float* bias;  float* target;
    if (bn < 2)      { W = Wq; bias = bq; target = g_Q; }
    else if (bn < 4) { W = Wk; bias = bk; target = g_K; }
    else             { W = Wv; bias = bv; target = g_V; }
    const int ncol0 = (bn & 1) * 128;

    float acc[4][4][4];
    #pragma unroll
    for (int i = 0; i < 4; i++)
        #pragma unroll
        for (int j = 0; j < 4; j++)
            #pragma unroll
            for (int k = 0; k < 4; k++) acc[i][j][k] = 0.0f;

    const int lr = tid >> 3;
    const int lc = (tid & 7) * 4;

    for (int kb = 0; kb < 256; kb += 32) {
        #pragma unroll
        for (int i = 0; i < 4; i++) {
            int r = lr + i * 32;
            int grow = bm * 128 + r;
            float4 v = make_float4(0.f, 0.f, 0.f, 0.f);
            if (grow < Nrows)
                v = *(const float4*)(h + (size_t)grow * 256 + kb + lc);
            uint32_t* s = &As[r * 36 + lc];
            s[0] = f2tf32(v.x); s[1] = f2tf32(v.y);
            s[2] = f2tf32(v.z); s[3] = f2tf32(v.w);
        }
        #pragma unroll
        for (int i = 0; i < 4; i++) {
            int r = lr + i * 32;
            float4 v = *(const float4*)(W + (size_t)(ncol0 + r) * 256 + kb + lc);
            uint32_t* s = &Bs[r * 36 + lc];
            s[0] = f2tf32(v.x); s[1] = f2tf32(v.y);
            s[2] = f2tf32(v.z); s[3] = f2tf32(v.w);
        }
        __syncthreads();

        #pragma unroll
        for (int ks = 0; ks < 4; ks++) {
            const int k0 = ks * 8;
            uint32_t a[4][4], b[4][2];
            #pragma unroll
            for (int mt = 0; mt < 4; mt++) {
                int r = wm * 64 + mt * 16 + (lane >> 2);
                int c = k0 + (lane & 3);
                a[mt][0] = As[r * 36 + c];
                a[mt][1] = As[(r + 8) * 36 + c];
                a[mt][2] = As[r * 36 + c + 4];
                a[mt][3] = As[(r + 8) * 36 + c + 4];
            }
            #pragma unroll
            for (int nt = 0; nt < 4; nt++) {
                int n = wn * 32 + nt * 8 + (lane >> 2);
                int c = k0 + (lane & 3);
                b[nt][0] = Bs[n * 36 + c];
                b[nt][1] = Bs[n * 36 + c + 4];
            }
            #pragma unroll
            for (int mt = 0; mt < 4; mt++)
                #pragma unroll
                for (int nt = 0; nt < 4; nt++)
                    asm volatile(
                        "mma.sync.aligned.m16n8k8.row.col.f32.tf32.tf32.f32 "
                        "{%0,%1,%2,%3}, {%4,%5,%6,%7}, {%8,%9}, {%0,%1,%2,%3};"
                        : "+f"(acc[mt][nt][0]), "+f"(acc[mt][nt][1]),
                          "+f"(acc[mt][nt][2]), "+f"(acc[mt][nt][3])
                        : "r"(a[mt][0]), "r"(a[mt][1]), "r"(a[mt][2]), "r"(a[mt][3]),
                          "r"(b[nt][0]), "r"(b[nt][1]));
        }
        __syncthreads();
    }

    #pragma unroll
    for (int mt = 0; mt < 4; mt++) {
        int r0 = wm * 64 + mt * 16 + (lane >> 2);
        #pragma unroll
        for (int nt = 0; nt < 4; nt++) {
            int c0 = wn * 32 + nt * 8 + (lane & 3) * 2;
            #pragma unroll
            for (int cc = 0; cc < 4; cc++) {
                int r = r0 + ((cc >= 2) ? 8 : 0);
                int c = c0 + (cc & 1);
                int grow = bm * 128 + r;
                if (grow < Nrows) {
                    int j = ncol0 + c;
                    target[(size_t)grow * 256 + j] = acc[mt][nt][cc] + bias[j];
                }
            }
        }
    }
}

// ---------------------------------------------------------------------------
// Kernel 2: single-pass fused attention.  One warp per destination node.
//   out[d] = (sum_e sc_e * V[src_e]) / z,   z = sum_e sc_e     (per head)
// Butterfly reduction makes scores uniform per 8-lane head group, so z and
// the weighting are register-local: no score scratch, no second pass.
// ---------------------------------------------------------------------------
__global__ __launch_bounds__(256) void attn_fused(
    float* __restrict__ out, int n_nodes)
{
    const int node = (blockIdx.x * blockDim.x + threadIdx.x) >> 5;
    if (node >= n_nodes) return;
    const int lane = threadIdx.x & 31;
    const unsigned FULL = 0xffffffffu;
    const float inv = 0.17677669529663687f;   // 1/sqrt(32)

    const int beg = g_rowptr[node];
    const int end = g_rowptr[node + 1];

    // Q row register-resident: lane covers channels [4*lane..4*lane+3], +128
    const float4* Qr = (const float4*)(g_Q + (size_t)node * 256);
    const float4 q0 = Qr[lane];
    const float4 q1 = Qr[lane + 32];

    float4 acc0 = make_float4(0.f, 0.f, 0.f, 0.f);
    float4 acc1 = make_float4(0.f, 0.f, 0.f, 0.f);
    float z0 = 0.0f, z1 = 0.0f;               // uniform within head group

    for (int i = beg; i < end; i++) {
        const int s = g_csr_src[i];
        const float4* Kr = (const float4*)(g_K + (size_t)s * 256);
        const float4* Vr = (const float4*)(g_V + (size_t)s * 256);
        float4 k0 = Kr[lane];
        float4 k1 = Kr[lane + 32];
        float4 v0 = Vr[lane];
        float4 v1 = Vr[lane + 32];

        float p0 = k0.x * q0.x + k0.y * q0.y + k0.z * q0.z + k0.w * q0.w;
        float p1 = k1.x * q1.x + k1.y * q1.y + k1.z * q1.z + k1.w * q1.w;
        #pragma unroll
        for (int off = 4; off; off >>= 1) {      // butterfly: all lanes get sum
            p0 += __shfl_xor_sync(FULL, p0, off);
            p1 += __shfl_xor_sync(FULL, p1, off);
        }
        float sc0 = __expf(fminf(fmaxf(p0 * inv, -5.0f), 5.0f));
        float sc1 = __expf(fminf(fmaxf(p1 * inv, -5.0f), 5.0f));
        z0 += sc0;
        z1 += sc1;

        acc0.x += sc0 * v0.x; acc0.y += sc0 * v0.y;
        acc0.z += sc0 * v0.z; acc0.w += sc0 * v0.w;
        acc1.x += sc1 * v1.x; acc1.y += sc1 * v1.y;
        acc1.z += sc1 * v1.z; acc1.w += sc1 * v1.w;
    }

    const float rz0 = (z0 > 0.0f) ? 1.0f / z0 : 0.0f;
    const float rz1 = (z1 > 0.0f) ? 1.0f / z1 : 0.0f;
    acc0.x *= rz0; acc0.y *= rz0; acc0.z *= rz0; acc0.w *= rz0;
    acc1.x *= rz1; acc1.y *= rz1; acc1.z *= rz1; acc1.w *= rz1;

    float4* o = (float4*)(out + (size_t)node * 256);
    o[lane]      = acc0;
    o[lane + 32] = acc1;
}

// ---------------------------------------------------------------------------
extern "C" void kernel_launch(void* const* d_in, const int* in_sizes, int n_in,
                              void* d_out, int out_size)
{
    const float* h  = (const float*)d_in[0];
    const float* Wq = (const float*)d_in[1];
    const float* bq = (const float*)d_in[2];
    const float* Wk = (const float*)d_in[3];
    const float* bk = (const float*)d_in[4];
    const float* Wv = (const float*)d_in[5];
    const float* bv = (const float*)d_in[6];
    const int*   src = (const int*)d_in[7];
    const int*   dst = (const int*)d_in[8];
    float* out = (float*)d_out;

    const int N = in_sizes[0] / 256;   // 50000
    const int E = in_sizes[7];         // 800000

    // CSR build
    zero_deg<<<(N + 255) / 256, 256>>>(N);
    hist_kernel<<<(E + 255) / 256, 256>>>(dst, E);
    scan_kernel<<<1, 1024>>>(N);
    scatter_kernel<<<(E + 255) / 256, 256>>>(src, dst, E);

    // QKV projections (TF32 tensor-core GEMM)
    dim3 grid((N + 127) / 128, 6);
    qkv_gemm<<<grid, 256>>>(h, Wq, bq, Wk, bk, Wv, bv, N);

    // Single-pass fused attention, one warp per dst node
    attn_fused<<<(N * 32 + 255) / 256, 256>>>(out, N);
}